// round 3
// baseline (speedup 1.0000x reference)
#include <cuda_runtime.h>
#include <math.h>

#define BB 4
#define TT 8
#define BT 32
#define DD 64
#define CC 128
#define HH 64
#define WW 64
#define HW 4096
#define NPOS 131072          // BT*HW
#define HID 512
#define OUT_OFF_H 16777216   // 2*B*T*D*H*W
#define OUT_OFF_F 18874368   // + 2*B*H*W*D

// ---------------- scratch (device globals; no allocations allowed) ----------
__device__ float g_xn[BT*CC*HW];          // LN output, (bt,ch,h,w)
__device__ float g_wT[CC*9*CC];           // conv weights transposed: (ic,tap,oc)
__device__ float g_xsp_re[NPOS*DD];       // (bt,d,hw)  d-major
__device__ float g_xsp_im[NPOS*DD];
__device__ float g_xeig_re[NPOS*DD];      // (pos,e) pos-major; reused as y in-place
__device__ float g_xeig_im[NPOS*DD];
__device__ float g_z_re[NPOS*DD];         // (pos,e)
__device__ float g_z_im[NPOS*DD];
__device__ float g_hdn[HID*NPOS];         // (hid,pos)
__device__ float g_xmean_re[BT*DD], g_xmean_im[BT*DD];
__device__ float g_ff_re[BT*DD],    g_ff_im[BT*DD];      // flux forcing
__device__ float g_src_re[BT*DD],   g_src_im[BT*DD];
__device__ float g_gate[BT*DD];
__device__ float g_ah_re[DD], g_ah_im[DD], g_ch_re[DD], g_ch_im[DD];
__device__ float g_af_re[DD], g_af_im[DD], g_cf_re[DD], g_cf_im[DD];

// ---------------------------------------------------------------- LayerNorm
__global__ void k_ln(const float* __restrict__ xre, const float* __restrict__ xim,
                     const float* __restrict__ gamma, const float* __restrict__ beta) {
    __shared__ float s[32*129];
    __shared__ float smu[32], srs[32];
    int bid = blockIdx.x;
    int bt  = bid >> 7;
    int rem = bid & 127;
    int h   = rem >> 1;
    int w0  = (rem & 1) << 5;
    int tid = threadIdx.x;
    for (int i = tid; i < 4096; i += 128) {
        int ch = i >> 5, p = i & 31;
        int d  = ch & 63;
        const float* src = (ch < 64) ? xre : xim;
        s[p*129 + ch] = src[((bt*64 + d)*64 + h)*64 + w0 + p];
    }
    __syncthreads();
    if (tid < 32) {
        float sum = 0.f, ss = 0.f;
        #pragma unroll 8
        for (int ch = 0; ch < 128; ++ch) { float v = s[tid*129 + ch]; sum += v; ss += v*v; }
        float mu  = sum * (1.0f/128.0f);
        float var = ss * (1.0f/128.0f) - mu*mu;
        smu[tid] = mu;
        srs[tid] = rsqrtf(var + 1e-5f);
    }
    __syncthreads();
    for (int i = tid; i < 4096; i += 128) {
        int ch = i >> 5, p = i & 31;
        float v = (s[p*129 + ch] - smu[p]) * srs[p] * gamma[ch] + beta[ch];
        g_xn[((bt*128 + ch)*64 + h)*64 + w0 + p] = v;
    }
}

// ------------------------------------------------- conv weight transpose
__global__ void k_wt(const float* __restrict__ cw) {
    int idx = blockIdx.x * 256 + threadIdx.x;   // 147456 total
    int oc = idx / 1152;
    int r  = idx - oc * 1152;                   // ic*9 + tap
    g_wT[r * 128 + oc] = cw[idx];
}

// -------------------------------------- conv 3x3 SAME + bias + metric + residual
__global__ void k_conv(const float* __restrict__ xre, const float* __restrict__ xim,
                       const float* __restrict__ cb, const float* __restrict__ metric) {
    __shared__ float s_in[800];     // 8 ic x 10 x 10
    __shared__ float s_w[9216];     // 8 ic x 9 tap x 128 oc
    int bt   = blockIdx.y;
    int tile = blockIdx.x;
    int ty0  = (tile >> 3) << 3;
    int tx0  = (tile & 7) << 3;
    int tid  = threadIdx.x;
    int og   = tid >> 4;            // 16 groups of 8 oc
    int pt   = tid & 15;            // 16 pos-threads -> 64 positions
    int ty   = pt >> 1;
    int txb  = (pt & 1) << 2;
    int ocb  = og << 3;
    float acc[8][4];
    #pragma unroll
    for (int o = 0; o < 8; ++o)
        #pragma unroll
        for (int j = 0; j < 4; ++j) acc[o][j] = 0.f;

    for (int ccik = 0; ccik < 16; ++ccik) {
        int ic0 = ccik << 3;
        __syncthreads();
        for (int i = tid; i < 800; i += 256) {
            int ic = i / 100; int r = i - ic*100;
            int yy = r / 10;  int xx = r - yy*10;
            int gy = ty0 + yy - 1, gx = tx0 + xx - 1;
            float v = 0.f;
            if (gy >= 0 && gy < 64 && gx >= 0 && gx < 64)
                v = g_xn[((bt*128 + ic0 + ic)*64 + gy)*64 + gx];
            s_in[i] = v;
        }
        for (int i = tid; i < 9216; i += 256)
            s_w[i] = g_wT[ic0*1152 + i];
        __syncthreads();
        #pragma unroll 1
        for (int ic = 0; ic < 8; ++ic) {
            #pragma unroll
            for (int ky = 0; ky < 3; ++ky) {
                #pragma unroll
                for (int kx = 0; kx < 3; ++kx) {
                    int ib = ic*100 + (ty+ky)*10 + txb + kx;
                    float v0 = s_in[ib+0], v1 = s_in[ib+1], v2 = s_in[ib+2], v3 = s_in[ib+3];
                    const float* wrow = &s_w[(ic*9 + ky*3 + kx)*128 + ocb];
                    #pragma unroll
                    for (int o = 0; o < 8; ++o) {
                        float w = wrow[o];
                        acc[o][0] += w*v0; acc[o][1] += w*v1;
                        acc[o][2] += w*v2; acc[o][3] += w*v3;
                    }
                }
            }
        }
    }
    int h = ty0 + ty;
    #pragma unroll
    for (int o = 0; o < 8; ++o) {
        int oc = ocb + o;
        int d  = oc & 63;
        float bias = cb[oc];
        #pragma unroll
        for (int j = 0; j < 4; ++j) {
            int w   = tx0 + txb + j;
            float v = (acc[o][j] + bias) * metric[h*64 + w];
            int idx = ((bt*64 + d)*64 + h)*64 + w;
            if (oc < 64) g_xsp_re[idx] = xre[idx] + v;
            else         g_xsp_im[idx] = xim[idx] + v;
        }
    }
}

// --------------------------- complex 64x64 GEMM over positions (E / Edec)
__device__ __forceinline__ void egemm_body(
    const float* __restrict__ inr, const float* __restrict__ ini,
    const float* __restrict__ Er,  const float* __restrict__ Ei,
    float* __restrict__ outr, float* __restrict__ outi, bool dmajor)
{
    extern __shared__ float sm[];
    float* sxr = sm;
    float* sxi = sm + 4160;
    float* ser = sm + 8320;
    float* sei = sm + 12480;
    int tid  = threadIdx.x;
    int pos0 = blockIdx.x << 6;
    int bt   = pos0 >> 12;
    int hw0  = pos0 & 4095;
    for (int i = tid; i < 4096; i += 256) {
        int d, p, g;
        if (dmajor) { d = i >> 6; p = i & 63; g = (bt*64 + d)*4096 + hw0 + p; }
        else        { p = i >> 6; d = i & 63; g = (pos0 + p)*64 + d; }
        sxr[d*65 + p] = inr[g];
        sxi[d*65 + p] = ini[g];
        int dd = i >> 6, e = i & 63;
        ser[dd*65 + e] = Er[i];
        sei[dd*65 + e] = Ei[i];
    }
    __syncthreads();
    int eg = tid >> 4, pt = tid & 15;
    int e0 = eg << 2,  p0 = pt << 2;
    float ar[4][4] = {}, ai[4][4] = {};
    #pragma unroll 4
    for (int d = 0; d < 64; ++d) {
        float vr[4], vi[4], er[4], ei_[4];
        #pragma unroll
        for (int j = 0; j < 4; ++j) {
            vr[j]  = sxr[d*65 + p0 + j];
            vi[j]  = sxi[d*65 + p0 + j];
            er[j]  = ser[d*65 + e0 + j];
            ei_[j] = sei[d*65 + e0 + j];
        }
        #pragma unroll
        for (int pj = 0; pj < 4; ++pj)
            #pragma unroll
            for (int ej = 0; ej < 4; ++ej) {
                ar[pj][ej] += vr[pj]*er[ej] - vi[pj]*ei_[ej];
                ai[pj][ej] += vr[pj]*ei_[ej] + vi[pj]*er[ej];
            }
    }
    #pragma unroll
    for (int pj = 0; pj < 4; ++pj) {
        int pos = pos0 + p0 + pj;
        *(float4*)(outr + pos*64 + e0) = make_float4(ar[pj][0], ar[pj][1], ar[pj][2], ar[pj][3]);
        *(float4*)(outi + pos*64 + e0) = make_float4(ai[pj][0], ai[pj][1], ai[pj][2], ai[pj][3]);
    }
}

__global__ void k_egemm1(const float* __restrict__ Er, const float* __restrict__ Ei) {
    egemm_body(g_xsp_re, g_xsp_im, Er, Ei, g_xeig_re, g_xeig_im, true);
}
__global__ void k_egemm2(const float* __restrict__ Er, const float* __restrict__ Ei) {
    egemm_body(g_xeig_re, g_xeig_im, Er, Ei, g_z_re, g_z_im, false);
}

// ----------------------------------------------- spatial mean of x_eig
__global__ void k_mean() {
    __shared__ float rr[256], ri[256];
    int bt = blockIdx.x, tid = threadIdx.x;
    int c = tid >> 6, e = tid & 63;
    float sr = 0.f, si = 0.f;
    int base = ((bt*4096 + c*1024)*64) + e;
    for (int i = 0; i < 1024; ++i) {
        sr += g_xeig_re[base + i*64];
        si += g_xeig_im[base + i*64];
    }
    rr[tid] = sr; ri[tid] = si;
    __syncthreads();
    if (c == 0) {
        sr = rr[e] + rr[64+e] + rr[128+e] + rr[192+e];
        si = ri[e] + ri[64+e] + ri[128+e] + ri[192+e];
        g_xmean_re[bt*64 + e] = sr * (1.0f/4096.0f);
        g_xmean_im[bt*64 + e] = si * (1.0f/4096.0f);
    }
}

// ----------------------------------------------- per-d recurrence constants
__global__ void k_consts(const float* __restrict__ dt,
                         const float* __restrict__ lhr, const float* __restrict__ lhi,
                         const float* __restrict__ lfr, const float* __restrict__ lfi) {
    int d = threadIdx.x;
    float t = dt[0];
    {
        float lr = -fabsf(lhr[d]), li = lhi[d];
        float m = expf(lr*t);
        float ar = m*cosf(li*t), ai = m*sinf(li*t);
        float nr = ar - 1.f, ni = ai;
        float den = lr*lr + li*li;
        g_ah_re[d] = ar; g_ah_im[d] = ai;
        g_ch_re[d] = (nr*lr + ni*li)/den;
        g_ch_im[d] = (ni*lr - nr*li)/den;
    }
    {
        float lr = -fabsf(lfr[d]), li = lfi[d];
        float m = expf(lr*t);
        float ar = m*cosf(li*t), ai = m*sinf(li*t);
        float nr = ar - 1.f, ni = ai;
        float den = lr*lr + li*li;
        g_af_re[d] = ar; g_af_im[d] = ai;
        g_cf_re[d] = (nr*lr + ni*li)/den;
        g_cf_im[d] = (ni*lr - nr*li)/den;
    }
}

// ----------------------------------------------- flux scan over T
__global__ void k_flux(const float* __restrict__ fpr, const float* __restrict__ fpi,
                       float* __restrict__ dout) {
    int tid = threadIdx.x;
    int b = tid >> 6, d = tid & 63;
    float ar = g_af_re[d], ai = g_af_im[d];
    float cr = g_cf_re[d], ci = g_cf_im[d];
    float sr = fpr[b*64 + d], si = fpi[b*64 + d];
    #pragma unroll
    for (int t = 0; t < 8; ++t) {
        int idx = (b*8 + t)*64 + d;
        g_ff_re[idx] = sr; g_ff_im[idx] = si;        // forcing = state BEFORE update
        float xr = g_xmean_re[idx], xi = g_xmean_im[idx];
        float ur = xr*cr - xi*ci, ui = xr*ci + xi*cr;
        float nsr = ar*sr - ai*si + ur;
        float nsi = ar*si + ai*sr + ui;
        sr = nsr; si = nsi;
    }
    dout[OUT_OFF_F + b*64 + d]       = sr;
    dout[OUT_OFF_F + 256 + b*64 + d] = si;
}

// ----------------------------------------------- source / gate
__global__ void k_srcgate(const float* __restrict__ Wsr, const float* __restrict__ Wsi,
                          const float* __restrict__ Wg,  const float* __restrict__ bg) {
    int bt = blockIdx.x;
    int e  = threadIdx.x;
    float sr = 0.f, si = 0.f, ga = 0.f;
    #pragma unroll 8
    for (int d = 0; d < 64; ++d) {
        float fr = g_ff_re[bt*64 + d], fi = g_ff_im[bt*64 + d];
        float wr = Wsr[d*64 + e], wi = Wsi[d*64 + e];
        sr += fr*wr - fi*wi;
        si += fr*wi + fi*wr;
        ga += fr*Wg[d*64 + e];
    }
    g_src_re[bt*64 + e] = sr;
    g_src_im[bt*64 + e] = si;
    g_gate[bt*64 + e]   = 1.f/(1.f + expf(-(ga + bg[e])));
}

// ----------------------------------------------- main recurrence (in-place), h_out
__global__ void k_rec(const float* __restrict__ hpr, const float* __restrict__ hpi,
                      float* __restrict__ dout) {
    int bid = blockIdx.x;            // b*4096 + hw
    int b = bid >> 12;
    int d = threadIdx.x;
    float ar = g_ah_re[d], ai = g_ah_im[d];
    float cr = g_ch_re[d], ci = g_ch_im[d];
    float yr = hpr[bid*64 + d], yi = hpi[bid*64 + d];
    int hw = bid & 4095;
    #pragma unroll
    for (int t = 0; t < 8; ++t) {
        int bt  = b*8 + t;
        int idx = (bt*4096 + hw)*64 + d;
        float xr = g_xeig_re[idx], xi = g_xeig_im[idx];
        float g  = g_gate[bt*64 + d];
        float sr = g_src_re[bt*64 + d], si = g_src_im[bt*64 + d];
        float fr = xr*g + sr*(1.f - g);
        float fi = xi*g + si*(1.f - g);
        float ur = fr*cr - fi*ci, ui = fr*ci + fi*cr;
        float nyr = ar*yr - ai*yi + ur;
        float nyi = ar*yi + ai*yr + ui;
        yr = nyr; yi = nyi;
        g_xeig_re[idx] = yr;
        g_xeig_im[idx] = yi;
    }
    dout[OUT_OFF_H + bid*64 + d]           = yr;
    dout[OUT_OFF_H + 1048576 + bid*64 + d] = yi;
}

// ----------------------------------------------- FFN
__device__ __forceinline__ float gelu_f(float x) {
    float x3 = x*x*x;
    return 0.5f*x*(1.f + tanhf(0.7978845608028654f*(x + 0.044715f*x3)));
}

__global__ void k_ffn1(const float* __restrict__ w1, const float* __restrict__ b1) {
    extern __shared__ float sm[];
    float* s_z = sm;            // 128 x 65
    float* s_w = sm + 8320;     // 128 x 128
    int tid  = threadIdx.x;
    int pos0 = blockIdx.x << 6;
    int hid0 = blockIdx.y << 7;
    for (int i = tid; i < 8192; i += 256) {
        int p = i >> 7, k = i & 127;
        float v = (k < 64) ? g_z_re[(pos0 + p)*64 + k] : g_z_im[(pos0 + p)*64 + k - 64];
        s_z[k*65 + p] = v;
    }
    for (int i = tid; i < 16384; i += 256) {
        int k = i >> 7, h = i & 127;
        s_w[i] = w1[k*512 + hid0 + h];
    }
    __syncthreads();
    int hg = tid >> 4, pt = tid & 15;
    int h0 = hg << 3, p0 = pt << 2;
    float acc[8][4] = {};
    #pragma unroll 4
    for (int k = 0; k < 128; ++k) {
        float v[4], w[8];
        #pragma unroll
        for (int j = 0; j < 4; ++j) v[j] = s_z[k*65 + p0 + j];
        #pragma unroll
        for (int o = 0; o < 8; ++o) w[o] = s_w[k*128 + h0 + o];
        #pragma unroll
        for (int o = 0; o < 8; ++o)
            #pragma unroll
            for (int j = 0; j < 4; ++j)
                acc[o][j] += w[o]*v[j];
    }
    #pragma unroll
    for (int o = 0; o < 8; ++o) {
        int hid = hid0 + h0 + o;
        float bb = b1[hid];
        float4 r;
        r.x = gelu_f(acc[o][0] + bb);
        r.y = gelu_f(acc[o][1] + bb);
        r.z = gelu_f(acc[o][2] + bb);
        r.w = gelu_f(acc[o][3] + bb);
        *(float4*)(g_hdn + hid*NPOS + pos0 + p0) = r;
    }
}

__global__ void k_ffn2(const float* __restrict__ w2, const float* __restrict__ b2,
                       float* __restrict__ dout) {
    extern __shared__ float sm[];
    float* s_h  = sm;               // 64 x 65
    float* s_w  = sm + 4160;        // 64 x 128
    float* s_zr = sm + 12352;       // 64 x 64
    float* s_zi = sm + 16448;       // 64 x 64
    int tid  = threadIdx.x;
    int pos0 = blockIdx.x << 6;
    for (int i = tid; i < 4096; i += 256) {
        int p = i >> 6, d = i & 63;
        s_zr[i] = g_z_re[(pos0 + p)*64 + d];
        s_zi[i] = g_z_im[(pos0 + p)*64 + d];
    }
    int ocg = tid >> 4, pt = tid & 15;
    int oc0 = ocg << 3, p0 = pt << 2;
    float acc[8][4] = {};
    for (int kc = 0; kc < 8; ++kc) {
        int k0 = kc << 6;
        __syncthreads();
        for (int i = tid; i < 4096; i += 256) {
            int k = i >> 6, p = i & 63;
            s_h[k*65 + p] = g_hdn[(k0 + k)*NPOS + pos0 + p];
        }
        for (int i = tid; i < 8192; i += 256) {
            int k = i >> 7, oc = i & 127;
            s_w[i] = w2[(k0 + k)*128 + oc];
        }
        __syncthreads();
        #pragma unroll 4
        for (int k = 0; k < 64; ++k) {
            float v[4], w[8];
            #pragma unroll
            for (int j = 0; j < 4; ++j) v[j] = s_h[k*65 + p0 + j];
            #pragma unroll
            for (int o = 0; o < 8; ++o) w[o] = s_w[k*128 + oc0 + o];
            #pragma unroll
            for (int o = 0; o < 8; ++o)
                #pragma unroll
                for (int j = 0; j < 4; ++j)
                    acc[o][j] += w[o]*v[j];
        }
    }
    int bt  = pos0 >> 12;
    int hw0 = pos0 & 4095;
    #pragma unroll
    for (int o = 0; o < 8; ++o) {
        int oc = oc0 + o;
        int d  = oc & 63;
        float bb = b2[oc];
        #pragma unroll
        for (int j = 0; j < 4; ++j) {
            int p    = p0 + j;
            int base = (bt*64 + d)*4096 + hw0 + p;
            float zv = (oc < 64) ? s_zr[p*64 + d] : s_zi[p*64 + d];
            float xv = (oc < 64) ? g_xsp_re[base] : g_xsp_im[base];
            dout[((oc < 64) ? 0 : 8388608) + base] = acc[o][j] + bb + zv + xv;
        }
    }
}

// ---------------------------------------------------------------- launch
extern "C" void kernel_launch(void* const* d_in, const int* in_sizes, int n_in,
                              void* d_out, int out_size) {
    const float* x_re    = (const float*)d_in[0];
    const float* x_im    = (const float*)d_in[1];
    const float* hp_re   = (const float*)d_in[2];
    const float* hp_im   = (const float*)d_in[3];
    const float* fp_re   = (const float*)d_in[4];
    const float* fp_im   = (const float*)d_in[5];
    const float* dt      = (const float*)d_in[6];
    const float* ln_g    = (const float*)d_in[7];
    const float* ln_b    = (const float*)d_in[8];
    const float* conv_w  = (const float*)d_in[9];
    const float* conv_b  = (const float*)d_in[10];
    const float* metric  = (const float*)d_in[11];
    const float* E_re    = (const float*)d_in[12];
    const float* E_im    = (const float*)d_in[13];
    const float* Ed_re   = (const float*)d_in[14];
    const float* Ed_im   = (const float*)d_in[15];
    const float* lh_re   = (const float*)d_in[16];
    const float* lh_im   = (const float*)d_in[17];
    const float* lf_re   = (const float*)d_in[18];
    const float* lf_im   = (const float*)d_in[19];
    const float* Ws_re   = (const float*)d_in[20];
    const float* Ws_im   = (const float*)d_in[21];
    const float* W_gate  = (const float*)d_in[22];
    const float* b_gate  = (const float*)d_in[23];
    const float* ffn_w1  = (const float*)d_in[24];
    const float* ffn_b1  = (const float*)d_in[25];
    const float* ffn_w2  = (const float*)d_in[26];
    const float* ffn_b2  = (const float*)d_in[27];
    float* out = (float*)d_out;

    cudaFuncSetAttribute(k_egemm1, cudaFuncAttributeMaxDynamicSharedMemorySize, 66560);
    cudaFuncSetAttribute(k_egemm2, cudaFuncAttributeMaxDynamicSharedMemorySize, 66560);
    cudaFuncSetAttribute(k_ffn1,   cudaFuncAttributeMaxDynamicSharedMemorySize, 98816);
    cudaFuncSetAttribute(k_ffn2,   cudaFuncAttributeMaxDynamicSharedMemorySize, 82176);

    k_ln<<<4096, 128>>>(x_re, x_im, ln_g, ln_b);
    k_wt<<<576, 256>>>(conv_w);
    k_conv<<<dim3(64, 32), 256>>>(x_re, x_im, conv_b, metric);
    k_egemm1<<<2048, 256, 66560>>>(E_re, E_im);
    k_mean<<<32, 256>>>();
    k_consts<<<1, 64>>>(dt, lh_re, lh_im, lf_re, lf_im);
    k_flux<<<1, 256>>>(fp_re, fp_im, out);
    k_srcgate<<<32, 64>>>(Ws_re, Ws_im, W_gate, b_gate);
    k_rec<<<16384, 64>>>(hp_re, hp_im, out);
    k_egemm2<<<2048, 256, 66560>>>(Ed_re, Ed_im);
    k_ffn1<<<dim3(2048, 4), 256, 98816>>>(ffn_w1, ffn_b1);
    k_ffn2<<<2048, 256, 82176>>>(ffn_w2, ffn_b2, out);
}